// round 1
// baseline (speedup 1.0000x reference)
#include <cuda_runtime.h>
#include <cuda_bf16.h>

// Problem: B=64, T=4096, D=256
//   mids[b,d]  = sum_e W[d,e] * q[b,e]
//   s[b,t]     = tanh( sum_d k[b,t,d]*mids[b,d] + bias )
//   e[b,t]     = exp(s[b,t]) * m[b,t]        (max-subtraction cancels: tanh bounded)
//   attn[b,t]  = e[b,t] / sum_t e[b,t]
//
// Inputs (metadata order): q[B,D], k[B,T,D], m[B,T], W[D,D], bias[1]
// Output: attn[B,T] float32

#define BATCH 64
#define TT    4096
#define DD    256

__device__ float g_mids[BATCH * DD];

// ---------------- Kernel A: mids = W @ q (per batch) ----------------
// grid = B, block = D threads. q[b] cached in smem; each thread computes one d.
__global__ void kA_mids(const float* __restrict__ q,
                        const float* __restrict__ W) {
    __shared__ float sq[DD];
    const int b = blockIdx.x;
    const int d = threadIdx.x;
    sq[d] = q[b * DD + d];
    __syncthreads();

    const float4* Wrow = reinterpret_cast<const float4*>(W + d * DD);
    const float4* qv   = reinterpret_cast<const float4*>(sq);
    float acc = 0.f;
#pragma unroll 16
    for (int i = 0; i < DD / 4; ++i) {
        float4 w = Wrow[i];
        float4 x = qv[i];
        acc += w.x * x.x + w.y * x.y + w.z * x.z + w.w * x.w;
    }
    g_mids[b * DD + d] = acc;
}

// ---------------- Kernel B: e[b,t] = exp(tanh(k.mids + bias)) * m ----------------
// grid = (T/8, B), block = 256 (8 warps). One warp per t.
// Each lane loads two float4 (coalesced 1KB row per warp), shuffle-reduce.
__global__ void kB_scores(const float* __restrict__ k,
                          const float* __restrict__ m,
                          const float* __restrict__ bias,
                          float* __restrict__ e_out) {
    __shared__ float smids[DD];
    const int b    = blockIdx.y;
    const int tid  = threadIdx.x;
    const int warp = tid >> 5;
    const int lane = tid & 31;

    smids[tid] = g_mids[b * DD + tid];
    __syncthreads();

    const int t = blockIdx.x * 8 + warp;

    const float4* krow = reinterpret_cast<const float4*>(
        k + ((size_t)b * TT + t) * DD);
    const float4* mv = reinterpret_cast<const float4*>(smids);

    // lane covers elements [4*lane .. 4*lane+3] and [128+4*lane .. 128+4*lane+3]
    float4 k0 = krow[lane];
    float4 k1 = krow[lane + 32];
    float4 m0 = mv[lane];
    float4 m1 = mv[lane + 32];

    float acc = k0.x * m0.x + k0.y * m0.y + k0.z * m0.z + k0.w * m0.w
              + k1.x * m1.x + k1.y * m1.y + k1.z * m1.z + k1.w * m1.w;

#pragma unroll
    for (int off = 16; off > 0; off >>= 1)
        acc += __shfl_down_sync(0xffffffffu, acc, off);

    if (lane == 0) {
        float s = tanhf(acc + bias[0]);
        float e = __expf(s) * m[(size_t)b * TT + t];
        e_out[(size_t)b * TT + t] = e;
    }
}

// ---------------- Kernel C: per-batch normalize (deterministic) ----------------
// grid = B, block = 256. Reads e row (16KB), block-reduce sum, divide in place.
__global__ void kC_norm(float* __restrict__ e_io) {
    __shared__ float warp_sums[8];
    const int b   = blockIdx.x;
    const int tid = threadIdx.x;
    float* row = e_io + (size_t)b * TT;

    float acc = 0.f;
    float vals[16];
#pragma unroll
    for (int i = 0; i < 16; ++i) {
        vals[i] = row[tid + i * 256];
        acc += vals[i];
    }
#pragma unroll
    for (int off = 16; off > 0; off >>= 1)
        acc += __shfl_down_sync(0xffffffffu, acc, off);
    if ((tid & 31) == 0) warp_sums[tid >> 5] = acc;
    __syncthreads();

    if (tid < 8) {
        float s = warp_sums[tid];
#pragma unroll
        for (int off = 4; off > 0; off >>= 1)
            s += __shfl_down_sync(0xffu, s, off);
        if (tid == 0) warp_sums[0] = s;
    }
    __syncthreads();
    const float inv = 1.f / warp_sums[0];

#pragma unroll
    for (int i = 0; i < 16; ++i)
        row[tid + i * 256] = vals[i] * inv;
}

extern "C" void kernel_launch(void* const* d_in, const int* in_sizes, int n_in,
                              void* d_out, int out_size) {
    const float* q    = (const float*)d_in[0];
    const float* k    = (const float*)d_in[1];
    const float* m    = (const float*)d_in[2];
    const float* W    = (const float*)d_in[3];
    const float* bias = (const float*)d_in[4];
    float* out = (float*)d_out;

    kA_mids<<<BATCH, DD>>>(q, W);
    dim3 gB(TT / 8, BATCH);
    kB_scores<<<gB, 256>>>(k, m, bias, out);
    kC_norm<<<BATCH, 256>>>(out);
}

// round 2
// speedup vs baseline: 1.2821x; 1.2821x over previous
#include <cuda_runtime.h>
#include <cuda_bf16.h>

// Problem: B=64, T=4096, D=256
//   mids[b,d]  = sum_e W[d,e] * q[b,e]
//   s[b,t]     = tanh( sum_d k[b,t,d]*mids[b,d] + bias )
//   e[b,t]     = exp(s[b,t]) * m[b,t]     (max-subtraction cancels: tanh bounded)
//   attn[b,t]  = e[b,t] / sum_t e[b,t]
//
// Inputs (metadata order): q[B,D], k[B,T,D], m[B,T], W[D,D], bias[1]
// Output: attn[B,T] float32

#define BATCH 64
#define TT    4096
#define DD    256

__device__ float g_mids[BATCH * DD];

// ---------------- Kernel A: mids = W @ q, warp-per-output ----------------
// grid = (D/8, B), block = 256 (8 warps). Warp w computes d = bx*8 + w for batch b.
// Each lane: 2 coalesced float4 loads of W row + smem q, shuffle reduce.
__global__ void kA_mids(const float* __restrict__ q,
                        const float* __restrict__ W) {
    __shared__ float sq[DD];
    const int b    = blockIdx.y;
    const int tid  = threadIdx.x;
    const int warp = tid >> 5;
    const int lane = tid & 31;

    sq[tid] = q[b * DD + tid];
    __syncthreads();

    const int d = blockIdx.x * 8 + warp;
    const float4* Wrow = reinterpret_cast<const float4*>(W + d * DD);
    const float4* qv   = reinterpret_cast<const float4*>(sq);

    float4 w0 = Wrow[lane];
    float4 w1 = Wrow[lane + 32];
    float4 x0 = qv[lane];
    float4 x1 = qv[lane + 32];

    float acc = w0.x * x0.x + w0.y * x0.y + w0.z * x0.z + w0.w * x0.w
              + w1.x * x1.x + w1.y * x1.y + w1.z * x1.z + w1.w * x1.w;

#pragma unroll
    for (int off = 16; off > 0; off >>= 1)
        acc += __shfl_down_sync(0xffffffffu, acc, off);

    if (lane == 0) g_mids[b * DD + d] = acc;
}

// ---------------- Kernel B: e[b,t] = exp(tanh(k.mids + bias)) * m ----------------
// grid = (T/16, B), block = 256 (8 warps). Two t's per warp -> 4 independent
// float4 global loads in flight per lane (MLP=4).
__global__ void kB_scores(const float* __restrict__ k,
                          const float* __restrict__ m,
                          const float* __restrict__ bias,
                          float* __restrict__ e_out) {
    __shared__ float smids[DD];
    const int b    = blockIdx.y;
    const int tid  = threadIdx.x;
    const int warp = tid >> 5;
    const int lane = tid & 31;

    smids[tid] = g_mids[b * DD + tid];
    __syncthreads();

    const int t0 = blockIdx.x * 16 + warp * 2;

    const float4* krow0 = reinterpret_cast<const float4*>(
        k + ((size_t)b * TT + t0) * DD);
    const float4* krow1 = krow0 + (DD / 4);
    const float4* mv = reinterpret_cast<const float4*>(smids);

    float4 a0 = krow0[lane];
    float4 a1 = krow0[lane + 32];
    float4 c0 = krow1[lane];
    float4 c1 = krow1[lane + 32];
    float4 m0 = mv[lane];
    float4 m1 = mv[lane + 32];

    float acc0 = a0.x * m0.x + a0.y * m0.y + a0.z * m0.z + a0.w * m0.w
               + a1.x * m1.x + a1.y * m1.y + a1.z * m1.z + a1.w * m1.w;
    float acc1 = c0.x * m0.x + c0.y * m0.y + c0.z * m0.z + c0.w * m0.w
               + c1.x * m1.x + c1.y * m1.y + c1.z * m1.z + c1.w * m1.w;

#pragma unroll
    for (int off = 16; off > 0; off >>= 1) {
        acc0 += __shfl_down_sync(0xffffffffu, acc0, off);
        acc1 += __shfl_down_sync(0xffffffffu, acc1, off);
    }

    if (lane == 0) {
        const float bb = bias[0];
        float s0 = tanhf(acc0 + bb);
        float s1 = tanhf(acc1 + bb);
        float e0 = __expf(s0) * m[(size_t)b * TT + t0];
        float e1 = __expf(s1) * m[(size_t)b * TT + t0 + 1];
        e_out[(size_t)b * TT + t0]     = e0;
        e_out[(size_t)b * TT + t0 + 1] = e1;
    }
}

// ---------------- Kernel C: per-batch normalize (deterministic) ----------------
// grid = B, block = 256. Reads e row (16KB), block-reduce sum, divide in place.
__global__ void kC_norm(float* __restrict__ e_io) {
    __shared__ float warp_sums[8];
    const int b   = blockIdx.x;
    const int tid = threadIdx.x;
    float* row = e_io + (size_t)b * TT;

    float acc = 0.f;
    float vals[16];
#pragma unroll
    for (int i = 0; i < 16; ++i) {
        vals[i] = row[tid + i * 256];
        acc += vals[i];
    }
#pragma unroll
    for (int off = 16; off > 0; off >>= 1)
        acc += __shfl_down_sync(0xffffffffu, acc, off);
    if ((tid & 31) == 0) warp_sums[tid >> 5] = acc;
    __syncthreads();

    if (tid < 8) {
        float s = warp_sums[tid];
#pragma unroll
        for (int off = 4; off > 0; off >>= 1)
            s += __shfl_down_sync(0xffu, s, off);
        if (tid == 0) warp_sums[0] = s;
    }
    __syncthreads();
    const float inv = 1.f / warp_sums[0];

#pragma unroll
    for (int i = 0; i < 16; ++i)
        row[tid + i * 256] = vals[i] * inv;
}

extern "C" void kernel_launch(void* const* d_in, const int* in_sizes, int n_in,
                              void* d_out, int out_size) {
    const float* q    = (const float*)d_in[0];
    const float* k    = (const float*)d_in[1];
    const float* m    = (const float*)d_in[2];
    const float* W    = (const float*)d_in[3];
    const float* bias = (const float*)d_in[4];
    float* out = (float*)d_out;

    dim3 gA(DD / 8, BATCH);
    kA_mids<<<gA, 256>>>(q, W);
    dim3 gB(TT / 16, BATCH);
    kB_scores<<<gB, 256>>>(k, m, bias, out);
    kC_norm<<<BATCH, 256>>>(out);
}

// round 3
// speedup vs baseline: 1.3441x; 1.0484x over previous
#include <cuda_runtime.h>
#include <cuda_bf16.h>

// Problem: B=64, T=4096, D=256
//   mids[b,d]  = sum_e W[d,e] * q[b,e]
//   s[b,t]     = tanh( sum_d k[b,t,d]*mids[b,d] + bias )
//   e[b,t]     = exp(s[b,t]) * m[b,t]     (max-subtraction cancels: tanh bounded)
//   attn[b,t]  = e[b,t] / sum_t e[b,t]
//
// Inputs: q[B,D], k[B,T,D], m[B,T], W[D,D], bias[1]   Output: attn[B,T] f32

#define BATCH 64
#define TT    4096
#define DD    256

__device__ float g_mids[BATCH * DD];

// ---------------- Kernel A: mids = W @ q, 4 outputs per warp (MLP=8) ----------
// grid = (D/32, B), block = 256 (8 warps). Warp w computes d_base..d_base+3.
__global__ void kA_mids(const float* __restrict__ q,
                        const float* __restrict__ W) {
    __shared__ float sq[DD];
    const int b    = blockIdx.y;
    const int tid  = threadIdx.x;
    const int warp = tid >> 5;
    const int lane = tid & 31;

    // Let the dependent kernel (kB) launch early; its pre-sync work doesn't
    // touch g_mids.
    cudaTriggerProgrammaticLaunchCompletion();

    sq[tid] = q[b * DD + tid];
    __syncthreads();

    const int d_base = blockIdx.x * 32 + warp * 4;
    const float4* qv = reinterpret_cast<const float4*>(sq);
    float4 x0 = qv[lane];
    float4 x1 = qv[lane + 32];

    float acc[4];
#pragma unroll
    for (int i = 0; i < 4; ++i) {
        const float4* Wrow = reinterpret_cast<const float4*>(W + (d_base + i) * DD);
        float4 w0 = Wrow[lane];
        float4 w1 = Wrow[lane + 32];
        acc[i] = w0.x * x0.x + w0.y * x0.y + w0.z * x0.z + w0.w * x0.w
               + w1.x * x1.x + w1.y * x1.y + w1.z * x1.z + w1.w * x1.w;
    }

#pragma unroll
    for (int off = 16; off > 0; off >>= 1) {
#pragma unroll
        for (int i = 0; i < 4; ++i)
            acc[i] += __shfl_down_sync(0xffffffffu, acc[i], off);
    }

    if (lane == 0) {
        float4 r = make_float4(acc[0], acc[1], acc[2], acc[3]);
        reinterpret_cast<float4*>(g_mids + b * DD + d_base)[0] = r;
    }
}

// ---------------- Kernel B: e[b,t] = exp(tanh(k.mids + bias)) * m -------------
// grid = (T/16, B), block = 256 (8 warps). Two t's per warp (MLP=4/lane).
// PDL secondary: k/m loads are issued BEFORE the grid-dependency sync.
__global__ void kB_scores(const float* __restrict__ k,
                          const float* __restrict__ m,
                          const float* __restrict__ bias,
                          float* __restrict__ e_out) {
    __shared__ float smids[DD];
    const int b    = blockIdx.y;
    const int tid  = threadIdx.x;
    const int warp = tid >> 5;
    const int lane = tid & 31;

    const int t0 = blockIdx.x * 16 + warp * 2;

    const float4* krow0 = reinterpret_cast<const float4*>(
        k + ((size_t)b * TT + t0) * DD);
    const float4* krow1 = krow0 + (DD / 4);

    // Independent of kA: issue these loads first to overlap kA's tail.
    float4 a0 = krow0[lane];
    float4 a1 = krow0[lane + 32];
    float4 c0 = krow1[lane];
    float4 c1 = krow1[lane + 32];
    float mw0 = 0.f, mw1 = 0.f;
    if (lane == 0) {
        mw0 = m[(size_t)b * TT + t0];
        mw1 = m[(size_t)b * TT + t0 + 1];
    }

    // Now wait for kA's g_mids to be visible.
    cudaGridDependencySynchronize();

    smids[tid] = g_mids[b * DD + tid];
    __syncthreads();

    const float4* mv = reinterpret_cast<const float4*>(smids);
    float4 m0 = mv[lane];
    float4 m1 = mv[lane + 32];

    float acc0 = a0.x * m0.x + a0.y * m0.y + a0.z * m0.z + a0.w * m0.w
               + a1.x * m1.x + a1.y * m1.y + a1.z * m1.z + a1.w * m1.w;
    float acc1 = c0.x * m0.x + c0.y * m0.y + c0.z * m0.z + c0.w * m0.w
               + c1.x * m1.x + c1.y * m1.y + c1.z * m1.z + c1.w * m1.w;

#pragma unroll
    for (int off = 16; off > 0; off >>= 1) {
        acc0 += __shfl_down_sync(0xffffffffu, acc0, off);
        acc1 += __shfl_down_sync(0xffffffffu, acc1, off);
    }

    if (lane == 0) {
        const float bb = bias[0];
        float e0 = __expf(tanhf(acc0 + bb)) * mw0;
        float e1 = __expf(tanhf(acc1 + bb)) * mw1;
        e_out[(size_t)b * TT + t0]     = e0;
        e_out[(size_t)b * TT + t0 + 1] = e1;
    }
}

// ---------------- Kernel C: per-batch normalize (float4, deterministic) -------
// grid = B, block = 256. 4 LDG.128/thread, block reduce, scale in place.
__global__ void kC_norm(float* __restrict__ e_io) {
    __shared__ float warp_sums[8];
    const int b   = blockIdx.x;
    const int tid = threadIdx.x;

    // kB never triggers early, so this fires at kB completion; only hides
    // launch latency.
    cudaGridDependencySynchronize();

    float4* row = reinterpret_cast<float4*>(e_io + (size_t)b * TT);

    float4 v[4];
#pragma unroll
    for (int i = 0; i < 4; ++i) v[i] = row[tid + i * 256];

    float acc = 0.f;
#pragma unroll
    for (int i = 0; i < 4; ++i)
        acc += v[i].x + v[i].y + v[i].z + v[i].w;

#pragma unroll
    for (int off = 16; off > 0; off >>= 1)
        acc += __shfl_down_sync(0xffffffffu, acc, off);
    if ((tid & 31) == 0) warp_sums[tid >> 5] = acc;
    __syncthreads();

    if (tid < 8) {
        float s = warp_sums[tid];
#pragma unroll
        for (int off = 4; off > 0; off >>= 1)
            s += __shfl_down_sync(0xffu, s, off);
        if (tid == 0) warp_sums[0] = s;
    }
    __syncthreads();
    const float inv = 1.f / warp_sums[0];

#pragma unroll
    for (int i = 0; i < 4; ++i) {
        v[i].x *= inv; v[i].y *= inv; v[i].z *= inv; v[i].w *= inv;
        row[tid + i * 256] = v[i];
    }
}

extern "C" void kernel_launch(void* const* d_in, const int* in_sizes, int n_in,
                              void* d_out, int out_size) {
    const float* q    = (const float*)d_in[0];
    const float* k    = (const float*)d_in[1];
    const float* m    = (const float*)d_in[2];
    const float* W    = (const float*)d_in[3];
    const float* bias = (const float*)d_in[4];
    float* out = (float*)d_out;

    // kA: plain launch
    {
        dim3 g(DD / 32, BATCH);
        kA_mids<<<g, 256>>>(q, W);
    }

    // kB: PDL secondary of kA
    {
        cudaLaunchAttribute at[1];
        at[0].id = cudaLaunchAttributeProgrammaticStreamSerialization;
        at[0].val.programmaticStreamSerializationAllowed = 1;
        cudaLaunchConfig_t cfg = {};
        cfg.gridDim  = dim3(TT / 16, BATCH);
        cfg.blockDim = dim3(256);
        cfg.stream   = 0;
        cfg.attrs    = at;
        cfg.numAttrs = 1;
        cudaLaunchKernelEx(&cfg, kB_scores, k, m, bias, out);
    }

    // kC: PDL secondary of kB (kB never triggers early -> launch-latency hiding only)
    {
        cudaLaunchAttribute at[1];
        at[0].id = cudaLaunchAttributeProgrammaticStreamSerialization;
        at[0].val.programmaticStreamSerializationAllowed = 1;
        cudaLaunchConfig_t cfg = {};
        cfg.gridDim  = dim3(BATCH);
        cfg.blockDim = dim3(256);
        cfg.stream   = 0;
        cfg.attrs    = at;
        cfg.numAttrs = 1;
        cudaLaunchKernelEx(&cfg, kC_norm, out);
    }
}